// round 5
// baseline (speedup 1.0000x reference)
#include <cuda_runtime.h>

#define NN 307
#define DD 64
#define EE 4912
#define TT 288
#define BB 8
#define NB 32          // persistent blocks: co-resident (<< SM count), cheap barrier
#define ITER 3         // ceil(307 / (NB*4)) node passes per block

// ---- scratch (device globals; zero-init at module load; no allocation) ----
__device__ float    g_p[NN * DD];      // projected features p = h @ W
__device__ float    g_ss[NN * 8];      // per-node src scores
__device__ float    g_st[NN * 8];      // per-node tgt scores
__device__ float    g_num[NN * DD];    // softmax-weighted numerator accum
__device__ float    g_den[NN * 8];     // softmax denominator accum
__device__ float    g_hout[NN * DD];   // final GAT output (read by k_big)
__device__ float    g_c[TT * DD];      // pe[t,d] + b_val[d]
__device__ unsigned g_cnt[8];          // barrier arrival counters (self-resetting)
__device__ unsigned g_flag[8];         // barrier sense flags (monotonic)

// --------------------------------------------------------------------------
// Self-resetting grid barrier, no init needed.
// Entrant snapshots flag BEFORE arriving; the flip requires this block's own
// arrival, so the snapshot can never see the new value => no lost-wakeup.
// Last arriver resets the counter (safe: barrier index used once per launch,
// launches are sequential), fences, then flips the flag (release).
// --------------------------------------------------------------------------
__device__ __forceinline__ void gbar(int i)
{
    __syncthreads();                       // block writes drained / visible
    if (threadIdx.x == 0) {
        volatile unsigned* f = &g_flag[i];
        unsigned s0 = *f;                  // snapshot sense
        __threadfence();                   // release this block's prior writes
        unsigned prev = atomicAdd(&g_cnt[i], 1u);
        if (prev == NB - 1) {
            g_cnt[i] = 0u;                 // reset for next launch
            __threadfence();
            atomicExch((unsigned*)f, s0 + 1u);   // release flip
        } else {
            while (*f == s0) {}
            __threadfence();               // acquire (CCTL.IVALL: drop stale L1)
        }
    }
    __syncthreads();
}

// --------------------------------------------------------------------------
// Edge phase: w = exp(leaky_relu(ss[src]+st[tgt])); num[tgt]+=w*p[src];
// den[tgt]+=w. Max-subtraction dropped: activations are O(0.1), exp cannot
// overflow; mathematically identical (validated rel_err ~1e-6 in R2/R3).
// One lane per (edge, d). __ldcg: read at L2 (coherence point for the REDs).
// --------------------------------------------------------------------------
template<int H, int F>
__device__ __forceinline__ void edge_phase(const int* __restrict__ ei)
{
#pragma unroll 4
    for (int idx = blockIdx.x * 256 + threadIdx.x;
         idx < EE * DD; idx += NB * 256) {
        int e = idx >> 6;
        int d = idx & 63;
        int h = d / F;                     // compile-time F -> shift
        int s = __ldg(&ei[e]);
        int t = __ldg(&ei[EE + e]);
        float ev = __ldcg(&g_ss[s * H + h]) + __ldcg(&g_st[t * H + h]);
        ev = ev > 0.f ? ev : 0.2f * ev;
        float w = __expf(ev);
        if ((d % F) == 0) atomicAdd(&g_den[t * H + h], w);
        atomicAdd(&g_num[t * DD + d], w * __ldcg(&g_p[s * DD + d]));
    }
}

// --------------------------------------------------------------------------
// Whole pre-k_big pipeline in ONE persistent kernel:
// PE table + node embedding + 3 GAT layers. h lives in shared across layers
// (each block owns ITER*4 fixed nodes). 6 grid barriers total.
// --------------------------------------------------------------------------
__global__ void __launch_bounds__(256, 1)
k_gat(const float* __restrict__ node_f, const int* __restrict__ ei,
      const float* __restrict__ b_val,
      const float* __restrict__ W_sta, const float* __restrict__ b_sta,
      const float* __restrict__ ada,
      const float* __restrict__ g0W, const float* __restrict__ g0as,
      const float* __restrict__ g0at, const float* __restrict__ g0b,
      const float* __restrict__ g1W, const float* __restrict__ g1as,
      const float* __restrict__ g1at, const float* __restrict__ g1b,
      const float* __restrict__ g2W, const float* __restrict__ g2as,
      const float* __restrict__ g2at, const float* __restrict__ g2b,
      const float* __restrict__ g0skip, const float* __restrict__ g1skip)
{
    __shared__ float sh[ITER][4][DD];   // h for this block's nodes, all layers
    __shared__ float sp[4][DD];         // per-pass projection scratch

    const int tid  = threadIdx.x;
    const int sub  = tid >> 6;
    const int lane = tid & 63;

    // --- PE table: g_c[t,d] = PE(t,d) + b_val[d] (independent, pre-barrier) ---
    for (int idx = blockIdx.x * 256 + tid; idx < TT * DD; idx += NB * 256) {
        int t = idx >> 6, d = idx & 63;
        float freq = __expf((float)(d & ~1) * (-9.210340371976184f / 64.0f));
        float s, c;
        __sincosf((float)t * freq, &s, &c);
        g_c[idx] = ((d & 1) ? c : s) + b_val[d];
    }

    // --- node-feature embedding: nf = node_f @ W_sta + b_sta + ada ---
#pragma unroll
    for (int it = 0; it < ITER; it++) {
        int n = it * (NB * 4) + blockIdx.x * 4 + sub;
        if (n < NN) {
            float acc = b_sta[lane] + ada[n * DD + lane];
#pragma unroll
            for (int k = 0; k < 32; k++)
                acc += node_f[n * 32 + k] * W_sta[k * DD + lane];
            sh[it][sub][lane] = acc;
        }
    }
    __syncthreads();

    // ================= 3 GAT layers =================
#pragma unroll
    for (int layer = 0; layer < 3; layer++) {
        const bool  l2   = (layer == 2);
        const int   H    = l2 ? 1 : 8;
        const int   F    = l2 ? 64 : 8;
        const float* W   = layer == 0 ? g0W  : layer == 1 ? g1W  : g2W;
        const float* as_ = layer == 0 ? g0as : layer == 1 ? g1as : g2as;
        const float* at_ = layer == 0 ? g0at : layer == 1 ? g1at : g2at;
        const float* bb  = layer == 0 ? g0b  : layer == 1 ? g1b  : g2b;
        const float* sk  = layer == 0 ? g0skip : g1skip;   // layer2: identity

        // ---- projection + attention scores ----
#pragma unroll
        for (int it = 0; it < ITER; it++) {
            int n = it * (NB * 4) + blockIdx.x * 4 + sub;
            bool act = n < NN;
            if (act) {
                float p = 0.f;
#pragma unroll
                for (int k = 0; k < DD; k++)
                    p += sh[it][sub][k] * W[k * DD + lane];
                g_p[n * DD + lane]   = p;
                g_num[n * DD + lane] = 0.f;
                sp[sub][lane] = p;
            }
            __syncthreads();
            if (act && lane < H) {
                float ssv = 0.f, stv = 0.f;
                for (int f = 0; f < F; f++) {
                    float v = sp[sub][lane * F + f];
                    ssv += v * as_[lane * F + f];
                    stv += v * at_[lane * F + f];
                }
                g_ss[n * H + lane]  = ssv;
                g_st[n * H + lane]  = stv;
                g_den[n * H + lane] = 0.f;
            }
            __syncthreads();
        }

        gbar(layer * 2);

        // ---- edge scatter ----
        if (l2) edge_phase<1, 64>(ei);
        else    edge_phase<8, 8>(ei);

        gbar(layer * 2 + 1);

        // ---- finalize: h = act(num/(den+eps) + skip + b) ----
        float v[ITER];
#pragma unroll
        for (int it = 0; it < ITER; it++) {
            int n = it * (NB * 4) + blockIdx.x * 4 + sub;
            if (n < NN) {
                float num = __ldcg(&g_num[n * DD + lane]);
                float den = __ldcg(&g_den[n * H + lane / F]);
                float val = num / (den + 1e-16f);
                float skip;
                if (l2) {
                    skip = sh[it][sub][lane];          // identity skip
                } else {
                    skip = 0.f;
#pragma unroll
                    for (int k = 0; k < DD; k++)
                        skip += sh[it][sub][k] * sk[k * DD + lane];
                }
                val += skip + bb[lane];
                if (!l2) val = val > 0.f ? val : (__expf(val) - 1.f);   // ELU
                v[it] = val;
            }
        }
        __syncthreads();   // done reading old sh
#pragma unroll
        for (int it = 0; it < ITER; it++) {
            int n = it * (NB * 4) + blockIdx.x * 4 + sub;
            if (n < NN) sh[it][sub][lane] = v[it];
        }
        __syncthreads();
    }

    // ---- publish final h ----
#pragma unroll
    for (int it = 0; it < ITER; it++) {
        int n = it * (NB * 4) + blockIdx.x * 4 + sub;
        if (n < NN) g_hout[n * DD + lane] = sh[it][sub][lane];
    }
}

// --------------------------------------------------------------------------
// Big broadcast kernel (the only HBM-heavy one):
// out[b,t,n,d] = x[b,t,n]*W_val[d] + c[t,d] + h[n,d], float4-vectorized.
// --------------------------------------------------------------------------
__global__ void k_big(const float* __restrict__ x,
                      const float* __restrict__ Wv,
                      float4* __restrict__ out, int total)
{
    int idx = blockIdx.x * blockDim.x + threadIdx.x;
    if (idx >= total) return;
    int dq   = idx & 15;
    int rest = idx >> 4;            // (b*T + t)*N + n
    int n    = rest % NN;
    int bt   = rest / NN;
    int t    = bt % TT;

    float xv = __ldg(&x[rest]);
    const float4 w  = ((const float4*)Wv)[dq];
    const float4 cc = ((const float4*)g_c)[t * 16 + dq];
    const float4 hh = ((const float4*)g_hout)[n * 16 + dq];

    float4 o;
    o.x = fmaf(xv, w.x, cc.x + hh.x);
    o.y = fmaf(xv, w.y, cc.y + hh.y);
    o.z = fmaf(xv, w.z, cc.z + hh.z);
    o.w = fmaf(xv, w.w, cc.w + hh.w);
    out[idx] = o;
}

extern "C" void kernel_launch(void* const* d_in, const int* in_sizes, int n_in,
                              void* d_out, int out_size)
{
    const float* x       = (const float*)d_in[0];
    const float* node_f  = (const float*)d_in[1];
    const int*   ei      = (const int*)d_in[2];
    // d_in[3] edge_prob unused
    const float* W_val   = (const float*)d_in[4];
    const float* b_val   = (const float*)d_in[5];
    const float* W_sta   = (const float*)d_in[6];
    const float* b_sta   = (const float*)d_in[7];
    const float* ada     = (const float*)d_in[8];
    const float* g0W     = (const float*)d_in[9];
    const float* g0as    = (const float*)d_in[10];
    const float* g0at    = (const float*)d_in[11];
    const float* g0b     = (const float*)d_in[12];
    const float* g1W     = (const float*)d_in[13];
    const float* g1as    = (const float*)d_in[14];
    const float* g1at    = (const float*)d_in[15];
    const float* g1b     = (const float*)d_in[16];
    const float* g2W     = (const float*)d_in[17];
    const float* g2as    = (const float*)d_in[18];
    const float* g2at    = (const float*)d_in[19];
    const float* g2b     = (const float*)d_in[20];
    const float* g0skip  = (const float*)d_in[21];
    const float* g1skip  = (const float*)d_in[22];

    // 1) PE table + node embedding + full GAT, one persistent kernel
    k_gat<<<NB, 256>>>(node_f, ei, b_val, W_sta, b_sta, ada,
                       g0W, g0as, g0at, g0b,
                       g1W, g1as, g1at, g1b,
                       g2W, g2as, g2at, g2b,
                       g0skip, g1skip);

    // 2) broadcast add (HBM-bound)
    int total = BB * TT * NN * 16;    // one thread per float4
    k_big<<<(total + 255) / 256, 256>>>(x, W_val, (float4*)d_out, total);
}

// round 6
// speedup vs baseline: 2.1495x; 2.1495x over previous
#include <cuda_runtime.h>

#define NN 307
#define DD 64
#define EE 4912
#define TT 288
#define BB 8
#define NODE_BLOCKS 77      // 77*4 = 308 >= 307 nodes, single wave
#define CH 24               // bt-chunk per k_big block (24 | 288: never crosses b)

// ---- scratch (device globals; no allocation allowed) ----
__device__ float g_h[NN * DD];      // layer activations (single buffer: node-private)
__device__ float g_p[NN * DD];      // projected features p = h @ W
__device__ float g_ss[NN * 8];      // per-node src scores
__device__ float g_st[NN * 8];      // per-node tgt scores
__device__ float g_num[NN * DD];    // softmax-weighted numerator accum
__device__ float g_den[NN * 8];     // softmax denominator accum
__device__ float g_hout[NN * DD];   // final GAT output (read by k_big)
__device__ float g_c[TT * DD];      // pe[t,d] + b_val[d]

// ==========================================================================
// Per-node building blocks. Block = 256 threads = 4 nodes (sub, lane).
// All __syncthreads are unconditional (inactive node 307 still participates).
// ==========================================================================

// proj: p = h @ W -> g_p (+smem), scores ss/st, zero accumulators for layer.
template<int H, int F>
__device__ __forceinline__ void proj(bool act, int n, int sub, int lane,
                                     const float* __restrict__ W,
                                     const float* __restrict__ as_,
                                     const float* __restrict__ at_,
                                     float (*sh)[DD], float (*sp)[DD])
{
    if (act) {
        float p = 0.f;
#pragma unroll
        for (int k = 0; k < DD; k++)
            p += sh[sub][k] * W[k * DD + lane];
        g_p[n * DD + lane]   = p;
        g_num[n * DD + lane] = 0.f;
        sp[sub][lane] = p;
    }
    __syncthreads();
    if (act && lane < H) {
        float ssv = 0.f, stv = 0.f;
#pragma unroll
        for (int f = 0; f < F; f++) {
            float v = sp[sub][lane * F + f];
            ssv += v * as_[lane * F + f];
            stv += v * at_[lane * F + f];
        }
        g_ss[n * H + lane]  = ssv;
        g_st[n * H + lane]  = stv;
        g_den[n * H + lane] = 0.f;
    }
}

// fin: val = [elu](num/(den+eps) + skip + b)
template<int H, int F, bool IDENT, bool ELU>
__device__ __forceinline__ float fin_val(int n, int sub, int lane,
                                         const float* __restrict__ skipW,
                                         const float* __restrict__ b,
                                         float (*sh)[DD])
{
    float num = g_num[n * DD + lane];
    float den = g_den[n * H + lane / F];
    float v = num / (den + 1e-16f);
    float skip;
    if (IDENT) {
        skip = sh[sub][lane];
    } else {
        skip = 0.f;
#pragma unroll
        for (int k = 0; k < DD; k++)
            skip += sh[sub][k] * skipW[k * DD + lane];
    }
    v += skip + b[lane];
    if (ELU) v = v > 0.f ? v : (__expf(v) - 1.f);
    return v;
}

// ==========================================================================
// K1: PE table + node embedding + proj/scores for layer 0.
// ==========================================================================
__global__ void __launch_bounds__(256)
k_first(const float* __restrict__ node_f, const float* __restrict__ b_val,
        const float* __restrict__ W_sta, const float* __restrict__ b_sta,
        const float* __restrict__ ada,
        const float* __restrict__ W, const float* __restrict__ as_,
        const float* __restrict__ at_)
{
    __shared__ float sh[4][DD];
    __shared__ float sp[4][DD];
    int tid  = threadIdx.x;
    int sub  = tid >> 6;
    int lane = tid & 63;
    int n    = blockIdx.x * 4 + sub;
    bool act = n < NN;

    // PE table: one element per thread (77*256 = 19712 >= 18432)
    int idx = blockIdx.x * 256 + tid;
    if (idx < TT * DD) {
        int t = idx >> 6, d = idx & 63;
        float freq = __expf((float)(d & ~1) * (-9.210340371976184f / 64.0f));
        float s, c;
        __sincosf((float)t * freq, &s, &c);
        g_c[idx] = ((d & 1) ? c : s) + b_val[d];
    }

    // node embedding: nf = node_f @ W_sta + b_sta + ada
    if (act) {
        float acc = b_sta[lane] + ada[n * DD + lane];
#pragma unroll
        for (int k = 0; k < 32; k++)
            acc += node_f[n * 32 + k] * W_sta[k * DD + lane];
        sh[sub][lane] = acc;
        g_h[n * DD + lane] = acc;
    }
    __syncthreads();

    proj<8, 8>(act, n, sub, lane, W, as_, at_, sh, sp);
}

// ==========================================================================
// K3/K5: finalize layer L, then proj/scores for layer L+1.
// ==========================================================================
template<int HI, int FI, int HO, int FO>
__global__ void __launch_bounds__(256)
k_mid(const float* __restrict__ skipW, const float* __restrict__ b,
      const float* __restrict__ W, const float* __restrict__ as_,
      const float* __restrict__ at_)
{
    __shared__ float sh[4][DD];
    __shared__ float sp[4][DD];
    int tid  = threadIdx.x;
    int sub  = tid >> 6;
    int lane = tid & 63;
    int n    = blockIdx.x * 4 + sub;
    bool act = n < NN;

    if (act) sh[sub][lane] = g_h[n * DD + lane];
    __syncthreads();

    float v = 0.f;
    if (act) v = fin_val<HI, FI, false, true>(n, sub, lane, skipW, b, sh);
    __syncthreads();                       // all fin reads of sh/g_den done
    if (act) {
        sh[sub][lane] = v;
        g_h[n * DD + lane] = v;
    }
    __syncthreads();

    proj<HO, FO>(act, n, sub, lane, W, as_, at_, sh, sp);
}

// ==========================================================================
// K7: finalize layer 2 (identity skip, no ELU) -> g_hout.
// ==========================================================================
__global__ void __launch_bounds__(256)
k_last(const float* __restrict__ b)
{
    __shared__ float sh[4][DD];
    int tid  = threadIdx.x;
    int sub  = tid >> 6;
    int lane = tid & 63;
    int n    = blockIdx.x * 4 + sub;
    bool act = n < NN;

    if (act) sh[sub][lane] = g_h[n * DD + lane];
    __syncthreads();
    if (act)
        g_hout[n * DD + lane] = fin_val<1, 64, true, false>(n, sub, lane, nullptr, b, sh);
}

// ==========================================================================
// Edge kernel: w = exp(leaky_relu(ss[src]+st[tgt])); num[tgt] += w*p[src];
// den[tgt] += w. Max-subtraction dropped (activations O(0.1): exp cannot
// overflow; identical math — validated rel_err ~1e-6 since R2).
// Plain loads: kernel boundary guarantees coherence, L1 caching helps reuse.
// ==========================================================================
template<int H, int F>
__global__ void __launch_bounds__(256)
k_edge(const int* __restrict__ ei)
{
    int idx = blockIdx.x * 256 + threadIdx.x;
    if (idx >= EE * DD) return;
    int e = idx >> 6;
    int d = idx & 63;
    int h = d / F;
    int s = __ldg(&ei[e]);
    int t = __ldg(&ei[EE + e]);
    float ev = g_ss[s * H + h] + g_st[t * H + h];
    ev = ev > 0.f ? ev : 0.2f * ev;
    float w = __expf(ev);
    if ((d % F) == 0) atomicAdd(&g_den[t * H + h], w);
    atomicAdd(&g_num[t * DD + d], w * g_p[s * DD + d]);
}

// ==========================================================================
// Big broadcast kernel: out[bt,n,d] = x[bt,n]*W[d] + c[t,d] + h[n,d].
// Thread owns one (n,dq) column: h[n,dq], W[dq] live in 8 registers.
// Loops over a CH-long bt range (grid.y). Per iter: 1 broadcast x load,
// 1 L1-hot c load, 1 128-bit store. No integer div/mod anywhere.
// ==========================================================================
__global__ void __launch_bounds__(256)
k_big(const float* __restrict__ x, const float* __restrict__ Wv,
      float4* __restrict__ out)
{
    int col  = blockIdx.x * 256 + threadIdx.x;   // n*16 + dq, 0..4911
    bool act = col < NN * 16;
    int dq   = col & 15;
    int n    = col >> 4;

    float4 w  = make_float4(0.f, 0.f, 0.f, 0.f);
    float4 hh = w;
    if (act) {
        w  = ((const float4*)Wv)[dq];
        hh = ((const float4*)g_hout)[col];
    }

    int bt0 = blockIdx.y * CH;
    int t0  = bt0 % TT;          // CH | TT: t runs t0..t0+CH-1, no wrap

    if (!act) return;
#pragma unroll 4
    for (int i = 0; i < CH; i++) {
        int bt = bt0 + i;
        float  xv = __ldg(&x[bt * NN + n]);
        float4 cc = ((const float4*)g_c)[(t0 + i) * 16 + dq];
        float4 o;
        o.x = fmaf(xv, w.x, cc.x + hh.x);
        o.y = fmaf(xv, w.y, cc.y + hh.y);
        o.z = fmaf(xv, w.z, cc.z + hh.z);
        o.w = fmaf(xv, w.w, cc.w + hh.w);
        out[bt * (NN * 16) + col] = o;
    }
}

extern "C" void kernel_launch(void* const* d_in, const int* in_sizes, int n_in,
                              void* d_out, int out_size)
{
    const float* x       = (const float*)d_in[0];
    const float* node_f  = (const float*)d_in[1];
    const int*   ei      = (const int*)d_in[2];
    // d_in[3] edge_prob unused
    const float* W_val   = (const float*)d_in[4];
    const float* b_val   = (const float*)d_in[5];
    const float* W_sta   = (const float*)d_in[6];
    const float* b_sta   = (const float*)d_in[7];
    const float* ada     = (const float*)d_in[8];
    const float* g0W     = (const float*)d_in[9];
    const float* g0as    = (const float*)d_in[10];
    const float* g0at    = (const float*)d_in[11];
    const float* g0b     = (const float*)d_in[12];
    const float* g1W     = (const float*)d_in[13];
    const float* g1as    = (const float*)d_in[14];
    const float* g1at    = (const float*)d_in[15];
    const float* g1b     = (const float*)d_in[16];
    const float* g2W     = (const float*)d_in[17];
    const float* g2as    = (const float*)d_in[18];
    const float* g2at    = (const float*)d_in[19];
    const float* g2b     = (const float*)d_in[20];
    const float* g0skip  = (const float*)d_in[21];
    const float* g1skip  = (const float*)d_in[22];

    const int EB = (EE * DD + 255) / 256;

    // GAT chain: 7 launches (ctab+embed+proj0 | edge | fin+proj ×2 | edge | fin)
    k_first<<<NODE_BLOCKS, 256>>>(node_f, b_val, W_sta, b_sta, ada, g0W, g0as, g0at);
    k_edge<8, 8><<<EB, 256>>>(ei);
    k_mid<8, 8, 8, 8><<<NODE_BLOCKS, 256>>>(g0skip, g0b, g1W, g1as, g1at);
    k_edge<8, 8><<<EB, 256>>>(ei);
    k_mid<8, 8, 1, 64><<<NODE_BLOCKS, 256>>>(g1skip, g1b, g2W, g2as, g2at);
    k_edge<1, 64><<<EB, 256>>>(ei);
    k_last<<<NODE_BLOCKS, 256>>>(g2b);

    // Broadcast add (HBM-store-bound): grid (col-tiles, bt-chunks)
    dim3 gb((NN * 16 + 255) / 256, (BB * TT) / CH);   // (20, 96)
    k_big<<<gb, 256>>>(x, W_val, (float4*)d_out);
}

// round 8
// speedup vs baseline: 2.5845x; 1.2024x over previous
#include <cuda_runtime.h>

#define NN 307
#define DD 64
#define EE 4912
#define TT 288
#define BB 8
#define NODE_BLOCKS 77      // 77*4 = 308 >= 307 nodes, single wave
#define CH 24               // bt-chunk per k_big block (24 | 288: never crosses b)

// ---- scratch (device globals; no allocation allowed) ----
__device__ float g_h[NN * DD];      // layer activations (node-private between kernels)
__device__ float g_p[NN * DD];      // projected features p = h @ W
__device__ float g_ss[NN * 8];      // per-node src scores
__device__ float g_st[NN * 8];      // per-node tgt scores
__device__ float g_num[NN * DD];    // softmax-weighted numerator accum
__device__ float g_den[NN * 8];     // softmax denominator accum
__device__ float g_c[TT * DD];      // pe[t,d] + b_val[d]

// ==========================================================================
// Per-node building blocks. Block = 256 threads = 4 nodes (sub, lane).
// ==========================================================================
template<int H, int F>
__device__ __forceinline__ void proj(bool act, int n, int sub, int lane,
                                     const float* __restrict__ W,
                                     const float* __restrict__ as_,
                                     const float* __restrict__ at_,
                                     float (*sh)[DD], float (*sp)[DD])
{
    if (act) {
        float p = 0.f;
#pragma unroll
        for (int k = 0; k < DD; k++)
            p += sh[sub][k] * W[k * DD + lane];
        g_p[n * DD + lane]   = p;
        g_num[n * DD + lane] = 0.f;
        sp[sub][lane] = p;
    }
    __syncthreads();
    if (act && lane < H) {
        float ssv = 0.f, stv = 0.f;
#pragma unroll
        for (int f = 0; f < F; f++) {
            float v = sp[sub][lane * F + f];
            ssv += v * as_[lane * F + f];
            stv += v * at_[lane * F + f];
        }
        g_ss[n * H + lane]  = ssv;
        g_st[n * H + lane]  = stv;
        g_den[n * H + lane] = 0.f;
    }
}

template<int H, int F>
__device__ __forceinline__ float fin_val(int n, int sub, int lane,
                                         const float* __restrict__ skipW,
                                         const float* __restrict__ b,
                                         float (*sh)[DD])
{
    float num = g_num[n * DD + lane];
    float den = g_den[n * H + lane / F];
    float v = num / (den + 1e-16f);
    float skip = 0.f;
#pragma unroll
    for (int k = 0; k < DD; k++)
        skip += sh[sub][k] * skipW[k * DD + lane];
    v += skip + b[lane];
    return v > 0.f ? v : (__expf(v) - 1.f);    // ELU
}

// ==========================================================================
// K1: PE table + node embedding + proj/scores for layer 0.
// ==========================================================================
__global__ void __launch_bounds__(256)
k_first(const float* __restrict__ node_f, const float* __restrict__ b_val,
        const float* __restrict__ W_sta, const float* __restrict__ b_sta,
        const float* __restrict__ ada,
        const float* __restrict__ W, const float* __restrict__ as_,
        const float* __restrict__ at_)
{
    __shared__ float sh[4][DD];
    __shared__ float sp[4][DD];
    int tid  = threadIdx.x;
    int sub  = tid >> 6;
    int lane = tid & 63;
    int n    = blockIdx.x * 4 + sub;
    bool act = n < NN;

    // PE table (77*256 = 19712 >= 18432 elements)
    int idx = blockIdx.x * 256 + tid;
    if (idx < TT * DD) {
        int t = idx >> 6, d = idx & 63;
        float freq = __expf((float)(d & ~1) * (-9.210340371976184f / 64.0f));
        float s, c;
        __sincosf((float)t * freq, &s, &c);
        g_c[idx] = ((d & 1) ? c : s) + b_val[d];
    }

    if (act) {
        float acc = b_sta[lane] + ada[n * DD + lane];
#pragma unroll
        for (int k = 0; k < 32; k++)
            acc += node_f[n * 32 + k] * W_sta[k * DD + lane];
        sh[sub][lane] = acc;
        g_h[n * DD + lane] = acc;
    }
    __syncthreads();

    proj<8, 8>(act, n, sub, lane, W, as_, at_, sh, sp);
}

// ==========================================================================
// K3/K5: finalize layer L (ELU, projected skip), then proj for layer L+1.
// ==========================================================================
template<int HO, int FO>
__global__ void __launch_bounds__(256)
k_mid(const float* __restrict__ skipW, const float* __restrict__ b,
      const float* __restrict__ W, const float* __restrict__ as_,
      const float* __restrict__ at_)
{
    __shared__ float sh[4][DD];
    __shared__ float sp[4][DD];
    int tid  = threadIdx.x;
    int sub  = tid >> 6;
    int lane = tid & 63;
    int n    = blockIdx.x * 4 + sub;
    bool act = n < NN;

    if (act) sh[sub][lane] = g_h[n * DD + lane];
    __syncthreads();

    float v = 0.f;
    if (act) v = fin_val<8, 8>(n, sub, lane, skipW, b, sh);
    __syncthreads();
    if (act) {
        sh[sub][lane] = v;
        g_h[n * DD + lane] = v;       // layer-(L+1) input (identity skip source for L2)
    }
    __syncthreads();

    proj<HO, FO>(act, n, sub, lane, W, as_, at_, sh, sp);
}

// ==========================================================================
// Edge kernels. Max-subtraction dropped (activations O(0.1): exp cannot
// overflow; identical math — validated rel_err ~1e-6 since R2).
//
// Layers 0/1 (H=8,F=8): ONE THREAD PER (edge, head). Amortizes the
// ei/ss/st/exp latency chain over 2 float4 p-loads and 9 atomics.
// ==========================================================================
__global__ void __launch_bounds__(256)
k_edge8(const int* __restrict__ ei)
{
    int idx = blockIdx.x * 256 + threadIdx.x;    // e*8 + h
    if (idx >= EE * 8) return;
    int e = idx >> 3;
    int h = idx & 7;
    int s = __ldg(&ei[e]);
    int t = __ldg(&ei[EE + e]);
    float ev = g_ss[s * 8 + h] + g_st[t * 8 + h];
    ev = ev > 0.f ? ev : 0.2f * ev;
    float w = __expf(ev);

    const float4* p4 = (const float4*)g_p;
    float4 a = p4[s * 16 + h * 2];
    float4 c = p4[s * 16 + h * 2 + 1];
    float* nt = &g_num[t * DD + h * 8];
    atomicAdd(&g_den[t * 8 + h], w);
    atomicAdd(nt + 0, w * a.x);
    atomicAdd(nt + 1, w * a.y);
    atomicAdd(nt + 2, w * a.z);
    atomicAdd(nt + 3, w * a.w);
    atomicAdd(nt + 4, w * c.x);
    atomicAdd(nt + 5, w * c.y);
    atomicAdd(nt + 6, w * c.z);
    atomicAdd(nt + 7, w * c.w);
}

// Layer 2 (H=1,F=64): one thread per (edge, d-quad): 1 float4 p-load + 4 atomics.
__global__ void __launch_bounds__(256)
k_edge1(const int* __restrict__ ei)
{
    int idx = blockIdx.x * 256 + threadIdx.x;    // e*16 + dq
    if (idx >= EE * 16) return;
    int e  = idx >> 4;
    int dq = idx & 15;
    int s = __ldg(&ei[e]);
    int t = __ldg(&ei[EE + e]);
    float ev = g_ss[s] + g_st[t];
    ev = ev > 0.f ? ev : 0.2f * ev;
    float w = __expf(ev);

    float4 a = ((const float4*)g_p)[s * 16 + dq];
    float* nt = &g_num[t * DD + dq * 4];
    if (dq == 0) atomicAdd(&g_den[t], w);
    atomicAdd(nt + 0, w * a.x);
    atomicAdd(nt + 1, w * a.y);
    atomicAdd(nt + 2, w * a.z);
    atomicAdd(nt + 3, w * a.w);
}

// ==========================================================================
// Big broadcast kernel, with layer-2 finalize fused into the prologue:
//   h[n,dq] = num/(den+eps) + h_prev + b2      (identity skip, no ELU)
//   out[bt,n,dq] = x[bt,n]*W[dq] + c[t,dq] + h[n,dq]
// Thread owns one (n,dq) column; h/W in registers; streaming stores.
// ==========================================================================
__global__ void __launch_bounds__(256)
k_big(const float* __restrict__ x, const float* __restrict__ Wv,
      const float* __restrict__ b2, float4* __restrict__ out)
{
    int col  = blockIdx.x * 256 + threadIdx.x;   // n*16 + dq, 0..4911
    if (col >= NN * 16) return;
    int dq   = col & 15;
    int n    = col >> 4;

    // fused layer-2 finalize (identity skip, + b2, no ELU)
    float4 num = ((const float4*)g_num)[col];
    float  den = g_den[n] + 1e-16f;
    float4 hp  = ((const float4*)g_h)[col];
    float4 bb  = ((const float4*)b2)[dq];
    float4 hh;
    hh.x = num.x / den + hp.x + bb.x;
    hh.y = num.y / den + hp.y + bb.y;
    hh.z = num.z / den + hp.z + bb.z;
    hh.w = num.w / den + hp.w + bb.w;

    float4 w = ((const float4*)Wv)[dq];

    int bt0 = blockIdx.y * CH;
    int t0  = bt0 % TT;          // CH | TT: no wrap inside chunk

#pragma unroll 4
    for (int i = 0; i < CH; i++) {
        int bt = bt0 + i;
        float  xv = __ldg(&x[bt * NN + n]);
        float4 cc = ((const float4*)g_c)[(t0 + i) * 16 + dq];
        float4 o;
        o.x = fmaf(xv, w.x, cc.x + hh.x);
        o.y = fmaf(xv, w.y, cc.y + hh.y);
        o.z = fmaf(xv, w.z, cc.z + hh.z);
        o.w = fmaf(xv, w.w, cc.w + hh.w);
        __stcs(&out[bt * (NN * 16) + col], o);   // streaming: don't pollute L2
    }
}

extern "C" void kernel_launch(void* const* d_in, const int* in_sizes, int n_in,
                              void* d_out, int out_size)
{
    const float* x       = (const float*)d_in[0];
    const float* node_f  = (const float*)d_in[1];
    const int*   ei      = (const int*)d_in[2];
    // d_in[3] edge_prob unused
    const float* W_val   = (const float*)d_in[4];
    const float* b_val   = (const float*)d_in[5];
    const float* W_sta   = (const float*)d_in[6];
    const float* b_sta   = (const float*)d_in[7];
    const float* ada     = (const float*)d_in[8];
    const float* g0W     = (const float*)d_in[9];
    const float* g0as    = (const float*)d_in[10];
    const float* g0at    = (const float*)d_in[11];
    const float* g0b     = (const float*)d_in[12];
    const float* g1W     = (const float*)d_in[13];
    const float* g1as    = (const float*)d_in[14];
    const float* g1at    = (const float*)d_in[15];
    const float* g1b     = (const float*)d_in[16];
    const float* g2W     = (const float*)d_in[17];
    const float* g2as    = (const float*)d_in[18];
    const float* g2at    = (const float*)d_in[19];
    const float* g2b     = (const float*)d_in[20];
    const float* g0skip  = (const float*)d_in[21];
    const float* g1skip  = (const float*)d_in[22];

    // GAT chain: 5 launches + fused finalize in k_big
    k_first<<<NODE_BLOCKS, 256>>>(node_f, b_val, W_sta, b_sta, ada, g0W, g0as, g0at);
    k_edge8<<<(EE * 8 + 255) / 256, 256>>>(ei);
    k_mid<8, 8><<<NODE_BLOCKS, 256>>>(g0skip, g0b, g1W, g1as, g1at);
    k_edge8<<<(EE * 8 + 255) / 256, 256>>>(ei);
    k_mid<1, 64><<<NODE_BLOCKS, 256>>>(g1skip, g1b, g2W, g2as, g2at);
    k_edge1<<<(EE * 16 + 255) / 256, 256>>>(ei);

    // Broadcast add (HBM-store-bound) + layer-2 finalize
    dim3 gb((NN * 16 + 255) / 256, (BB * TT) / CH);   // (20, 96)
    k_big<<<gb, 256>>>(x, W_val, g2b, (float4*)d_out);
}